// round 6
// baseline (speedup 1.0000x reference)
#include <cuda_runtime.h>
#include <cuda_bf16.h>
#include <cstdint>

// ColBERT MaxSim via mma.sync bf16 HMMA, 2 CTAs/SM for latency hiding.
//   scores[b,c] = sum_n max_s dot(qs[b,n,:], ps[c,s,:])
// qs: (64,32,128) fp32, ps: (64,1024,128) fp32, out: (64,64) fp32.
//
// Kernel 0: convert qs -> bf16 global scratch.
// Kernel 1: grid (64 c, 4 quarter). CTA stages p[c, qq*256.., :] as bf16 (padded),
//   loops 16 A-tiles of 128 q-rows (cp.async, single buffer; the co-resident CTA
//   hides the stage latency), computes 128x256 sim with HMMA, stores per-(qrow)
//   col-group maxes straight to global.
// Kernel 2: max over 8 partials (4 quarters x 2 col groups), warp-sum over n.

#define DIM 128
#define ROWB 272          // padded bf16 row: 136 bf16 = 272 B -> ldmatrix conflict-free
#define QTOK 256          // doc tokens per CTA
#define QROWS 2048        // 64 b * 32 n
#define NTILES 16
#define NTHREADS 256

#define P_OFF 0
#define A_OFF  (QTOK * ROWB)                // 69632
#define SM_TOTAL (A_OFF + 128 * ROWB)       // 104448  -> 2 CTAs/SM

__device__ float g_part[64 * 4 * 2 * QROWS];   // [c][qq][wc][qrow]
__device__ __nv_bfloat16 g_qbf[QROWS * DIM];

__device__ __forceinline__ uint32_t smem_u32(const void* p) {
    uint32_t a;
    asm("{ .reg .u64 t; cvta.to.shared.u64 t, %1; cvt.u32.u64 %0, t; }" : "=r"(a) : "l"(p));
    return a;
}

#define LDSM_X4(r, addr) \
    asm volatile("ldmatrix.sync.aligned.m8n8.x4.shared.b16 {%0,%1,%2,%3}, [%4];" \
                 : "=r"((r)[0]), "=r"((r)[1]), "=r"((r)[2]), "=r"((r)[3]) : "r"(addr))

#define MMA_16816(d, a, b) \
    asm volatile("mma.sync.aligned.m16n8k16.row.col.f32.bf16.bf16.f32 " \
                 "{%0,%1,%2,%3}, {%4,%5,%6,%7}, {%8,%9}, {%0,%1,%2,%3};" \
                 : "+f"((d)[0]), "+f"((d)[1]), "+f"((d)[2]), "+f"((d)[3]) \
                 : "r"((a)[0]), "r"((a)[1]), "r"((a)[2]), "r"((a)[3]), \
                   "r"((b)[0]), "r"((b)[1]))

#define CP_ASYNC16(dst, src) \
    asm volatile("cp.async.cg.shared.global [%0], [%1], 16;" :: "r"(dst), "l"(src) : "memory")
#define CP_COMMIT()  asm volatile("cp.async.commit_group;" ::: "memory")
#define CP_WAIT0()   asm volatile("cp.async.wait_group 0;" ::: "memory")

// Convert a ROWS x 128 fp32 row-major tile into bf16 padded smem (stride ROWB bytes).
template<int ROWS>
__device__ __forceinline__ void stage_bf16(char* sm_dst, const float* __restrict__ src) {
    const int tid = threadIdx.x;
    #pragma unroll
    for (int i = tid; i < ROWS * 16; i += NTHREADS) {
        int row = i >> 4;
        int c8  = (i & 15) << 3;
        const float4* s4 = reinterpret_cast<const float4*>(src + row * DIM + c8);
        float4 v0 = s4[0];
        float4 v1 = s4[1];
        __nv_bfloat162 b0 = __floats2bfloat162_rn(v0.x, v0.y);
        __nv_bfloat162 b1 = __floats2bfloat162_rn(v0.z, v0.w);
        __nv_bfloat162 b2 = __floats2bfloat162_rn(v1.x, v1.y);
        __nv_bfloat162 b3 = __floats2bfloat162_rn(v1.z, v1.w);
        uint4 packed;
        packed.x = *reinterpret_cast<uint32_t*>(&b0);
        packed.y = *reinterpret_cast<uint32_t*>(&b1);
        packed.z = *reinterpret_cast<uint32_t*>(&b2);
        packed.w = *reinterpret_cast<uint32_t*>(&b3);
        *reinterpret_cast<uint4*>(sm_dst + row * ROWB + c8 * 2) = packed;
    }
}

// Async-stage a 128 x 128 bf16 tile (contiguous 256B rows) into padded smem.
__device__ __forceinline__ void stage_A_async(uint32_t a_dst, const __nv_bfloat16* src) {
    const int tid = threadIdx.x;
    #pragma unroll
    for (int i = tid; i < 128 * 16; i += NTHREADS) {
        int row = i >> 4;
        int cb  = (i & 15) << 4;
        CP_ASYNC16(a_dst + row * ROWB + cb,
                   reinterpret_cast<const char*>(src) + row * 256 + cb);
    }
}

__global__ __launch_bounds__(256, 4)
void convert_q_kernel(const float* __restrict__ qs, __nv_bfloat16* __restrict__ qbf) {
    int i = blockIdx.x * blockDim.x + threadIdx.x;
    const float4* s4 = reinterpret_cast<const float4*>(qs) + i * 2;
    float4 v0 = s4[0];
    float4 v1 = s4[1];
    __nv_bfloat162 b0 = __floats2bfloat162_rn(v0.x, v0.y);
    __nv_bfloat162 b1 = __floats2bfloat162_rn(v0.z, v0.w);
    __nv_bfloat162 b2 = __floats2bfloat162_rn(v1.x, v1.y);
    __nv_bfloat162 b3 = __floats2bfloat162_rn(v1.z, v1.w);
    uint4 packed;
    packed.x = *reinterpret_cast<uint32_t*>(&b0);
    packed.y = *reinterpret_cast<uint32_t*>(&b1);
    packed.z = *reinterpret_cast<uint32_t*>(&b2);
    packed.w = *reinterpret_cast<uint32_t*>(&b3);
    reinterpret_cast<uint4*>(qbf)[i] = packed;
}

__global__ __launch_bounds__(NTHREADS, 2)
void colbert_hmma_kernel(const __nv_bfloat16* __restrict__ qbf,
                         const float* __restrict__ ps,
                         float* __restrict__ part) {
    extern __shared__ char sm[];

    const int c = blockIdx.x;
    const int qq = blockIdx.y;    // token quarter
    const int tid = threadIdx.x;
    const int lane = tid & 31;
    const int wid = tid >> 5;
    const int wr = wid & 3;       // row group: rows [wr*32, +32)
    const int wc = wid >> 2;      // col group: 32 cols within each 64-col nb

    const uint32_t smem_base = smem_u32(sm);
    const uint32_t p_base = smem_base + P_OFF;
    const uint32_t a_base = smem_base + A_OFF;

    // Kick off A tile 0 (async), then stage the 256-token p quarter (fp32 -> bf16).
    stage_A_async(a_base, qbf);
    CP_COMMIT();
    const float* pg = ps + ((size_t)c * 1024 + (size_t)qq * QTOK) * DIM;
    stage_bf16<QTOK>(sm + P_OFF, pg);

    // ldmatrix lane addressing.
    const uint32_t a_lane_off = (uint32_t)((lane & 15) * ROWB + (lane >> 4) * 16);
    const int bgrp = lane >> 3;
    const uint32_t b_lane_off = (uint32_t)(((bgrp >> 1) * 8 + (lane & 7)) * ROWB + (bgrp & 1) * 16);

    float* pout = part + ((size_t)(c * 4 + qq) * 2 + wc) * QROWS;

    #pragma unroll 1
    for (int t = 0; t < NTILES; t++) {
        CP_WAIT0();        // A[t] landed (this thread's copies)
        __syncthreads();   // everyone's copies visible; P ready (t=0)

        float rm[2][2] = {{-3.0e38f, -3.0e38f}, {-3.0e38f, -3.0e38f}};

        #pragma unroll 1
        for (int nb = 0; nb < 4; nb++) {
            const int col0 = nb * 64 + wc * 32;
            float acc[2][4][4];
            #pragma unroll
            for (int mt = 0; mt < 2; mt++)
                #pragma unroll
                for (int nt = 0; nt < 4; nt++)
                    #pragma unroll
                    for (int i = 0; i < 4; i++) acc[mt][nt][i] = 0.0f;

            #pragma unroll
            for (int kc = 0; kc < 2; kc++) {
                // A fragments for this k-chunk: 2 m-tiles x 4 k-steps x 4 regs.
                uint32_t af[2][4][4];
                #pragma unroll
                for (int mt = 0; mt < 2; mt++)
                    #pragma unroll
                    for (int ks = 0; ks < 4; ks++) {
                        uint32_t addr = a_base
                                      + (uint32_t)((wr * 32 + mt * 16) * ROWB
                                                   + (kc * 4 + ks) * 32)
                                      + a_lane_off;
                        LDSM_X4(af[mt][ks], addr);
                    }
                #pragma unroll
                for (int ks = 0; ks < 4; ks++) {
                    uint32_t bf[4][2];
                    uint32_t b0 = p_base
                                + (uint32_t)(col0 * ROWB + (kc * 4 + ks) * 32)
                                + b_lane_off;
                    uint32_t r[4];
                    LDSM_X4(r, b0);
                    bf[0][0] = r[0]; bf[0][1] = r[1]; bf[1][0] = r[2]; bf[1][1] = r[3];
                    LDSM_X4(r, b0 + 16 * ROWB);
                    bf[2][0] = r[0]; bf[2][1] = r[1]; bf[3][0] = r[2]; bf[3][1] = r[3];
                    #pragma unroll
                    for (int mt = 0; mt < 2; mt++)
                        #pragma unroll
                        for (int nt = 0; nt < 4; nt++)
                            MMA_16816(acc[mt][nt], af[mt][ks], bf[nt]);
                }
            }

            #pragma unroll
            for (int mt = 0; mt < 2; mt++)
                #pragma unroll
                for (int nt = 0; nt < 4; nt++) {
                    rm[mt][0] = fmaxf(rm[mt][0], fmaxf(acc[mt][nt][0], acc[mt][nt][1]));
                    rm[mt][1] = fmaxf(rm[mt][1], fmaxf(acc[mt][nt][2], acc[mt][nt][3]));
                }
        }

        __syncthreads();   // all warps done reading A[t] -> buffer reusable
        if (t + 1 < NTILES)
            stage_A_async(a_base, qbf + (size_t)(t + 1) * 128 * DIM);
        CP_COMMIT();

        // Reduce across the 4 lanes sharing each row; store partial maxes.
        #pragma unroll
        for (int mt = 0; mt < 2; mt++)
            #pragma unroll
            for (int h = 0; h < 2; h++) {
                float v = rm[mt][h];
                v = fmaxf(v, __shfl_xor_sync(0xffffffffu, v, 1));
                v = fmaxf(v, __shfl_xor_sync(0xffffffffu, v, 2));
                if ((lane & 3) == 0) {
                    int qrow = t * 128 + wr * 32 + mt * 16 + h * 8 + (lane >> 2);
                    pout[qrow] = v;
                }
            }
    }
}

__global__ __launch_bounds__(256, 4)
void colbert_combine_kernel(const float* __restrict__ part, float* __restrict__ out) {
    int idx = blockIdx.x * blockDim.x + threadIdx.x;   // 0 .. 64*64*32-1
    int n = idx & 31;
    int c = (idx >> 5) & 63;
    int b = idx >> 11;
    int qrow = b * 32 + n;
    float m = -3.0e38f;
    #pragma unroll
    for (int p8 = 0; p8 < 8; p8++)
        m = fmaxf(m, part[((size_t)(c * 8 + p8)) * QROWS + qrow]);
    #pragma unroll
    for (int o = 16; o; o >>= 1) m += __shfl_xor_sync(0xffffffffu, m, o);
    if (n == 0) out[b * 64 + c] = m;
}

extern "C" void kernel_launch(void* const* d_in, const int* in_sizes, int n_in,
                              void* d_out, int out_size) {
    const float* qs = (const float*)d_in[0];   // (64, 32, 128)
    const float* ps = (const float*)d_in[1];   // (64, 1024, 128)
    float* out = (float*)d_out;                // (64, 64)

    float* part;
    cudaGetSymbolAddress((void**)&part, g_part);
    __nv_bfloat16* qbf;
    cudaGetSymbolAddress((void**)&qbf, g_qbf);

    convert_q_kernel<<<(QROWS * DIM / 8) / 256, 256>>>(qs, qbf);

    cudaFuncSetAttribute(colbert_hmma_kernel,
                         cudaFuncAttributeMaxDynamicSharedMemorySize, SM_TOTAL);
    dim3 grid(64, 4);
    colbert_hmma_kernel<<<grid, NTHREADS, SM_TOTAL>>>(qbf, ps, part);
    colbert_combine_kernel<<<(64 * 64 * 32) / 256, 256>>>(part, out);
}

// round 7
// speedup vs baseline: 1.0609x; 1.0609x over previous
#include <cuda_runtime.h>
#include <cuda_bf16.h>
#include <cstdint>

// ColBERT MaxSim via mma.sync bf16 HMMA — single persistent kernel.
//   scores[b,c] = sum_n max_s dot(qs[b,n,:], ps[c,s,:])
// qs: (64,32,128) fp32, ps: (64,1024,128) fp32, out: (64,64) fp32.
//
// grid (64 c, 2 half) = 128 CTAs, 1 CTA/SM, all resident.
// Phase A: each CTA converts its 16-row slice of qs -> g_qbf (bf16), bumps g_qctr.
// Phase B: stage p[c, half*512.., :] as bf16 into padded smem; spin until qs done.
// Phase C: 16 A-tiles (cp.async double-buffered) x HMMA 128x512; fold col maxes.
// Phase D: last CTA of each c pair combines halves, warp-sums n, writes out.

#define DIM 128
#define ROWB 272          // padded bf16 row: 136 bf16 = 272 B -> ldmatrix conflict-free
#define HALF_TOK 512
#define QROWS 2048        // 64 b * 32 n
#define NTILES 16
#define NTHREADS 256

#define P_OFF 0
#define A_OFF  (HALF_TOK * ROWB)            // 139264
#define A_SZ   (128 * ROWB)                 // 34816
#define SM_TOTAL (A_OFF + 2 * A_SZ)         // 208896

__device__ float g_part[64 * 2 * QROWS];
__device__ __nv_bfloat16 g_qbf[QROWS * DIM];
__device__ unsigned int g_qctr;        // monotonic across graph replays
__device__ unsigned int g_cctr[64];    // monotonic, parity = last of pair

__device__ __forceinline__ uint32_t smem_u32(const void* p) {
    uint32_t a;
    asm("{ .reg .u64 t; cvta.to.shared.u64 t, %1; cvt.u32.u64 %0, t; }" : "=r"(a) : "l"(p));
    return a;
}

#define LDSM_X4(r, addr) \
    asm volatile("ldmatrix.sync.aligned.m8n8.x4.shared.b16 {%0,%1,%2,%3}, [%4];" \
                 : "=r"((r)[0]), "=r"((r)[1]), "=r"((r)[2]), "=r"((r)[3]) : "r"(addr))

#define MMA_16816(d, a, b) \
    asm volatile("mma.sync.aligned.m16n8k16.row.col.f32.bf16.bf16.f32 " \
                 "{%0,%1,%2,%3}, {%4,%5,%6,%7}, {%8,%9}, {%0,%1,%2,%3};" \
                 : "+f"((d)[0]), "+f"((d)[1]), "+f"((d)[2]), "+f"((d)[3]) \
                 : "r"((a)[0]), "r"((a)[1]), "r"((a)[2]), "r"((a)[3]), \
                   "r"((b)[0]), "r"((b)[1]))

#define CP_ASYNC16(dst, src) \
    asm volatile("cp.async.cg.shared.global [%0], [%1], 16;" :: "r"(dst), "l"(src) : "memory")
#define CP_COMMIT()  asm volatile("cp.async.commit_group;" ::: "memory")
#define CP_WAIT0()   asm volatile("cp.async.wait_group 0;" ::: "memory")

// Convert a ROWS x 128 fp32 row-major tile into bf16 padded smem (stride ROWB bytes).
template<int ROWS>
__device__ __forceinline__ void stage_bf16(char* sm_dst, const float* __restrict__ src) {
    const int tid = threadIdx.x;
    #pragma unroll 4
    for (int i = tid; i < ROWS * 16; i += NTHREADS) {
        int row = i >> 4;
        int c8  = (i & 15) << 3;
        const float4* s4 = reinterpret_cast<const float4*>(src + row * DIM + c8);
        float4 v0 = s4[0];
        float4 v1 = s4[1];
        __nv_bfloat162 b0 = __floats2bfloat162_rn(v0.x, v0.y);
        __nv_bfloat162 b1 = __floats2bfloat162_rn(v0.z, v0.w);
        __nv_bfloat162 b2 = __floats2bfloat162_rn(v1.x, v1.y);
        __nv_bfloat162 b3 = __floats2bfloat162_rn(v1.z, v1.w);
        uint4 packed;
        packed.x = *reinterpret_cast<uint32_t*>(&b0);
        packed.y = *reinterpret_cast<uint32_t*>(&b1);
        packed.z = *reinterpret_cast<uint32_t*>(&b2);
        packed.w = *reinterpret_cast<uint32_t*>(&b3);
        *reinterpret_cast<uint4*>(sm_dst + row * ROWB + c8 * 2) = packed;
    }
}

// Async-stage a 128 x 128 bf16 tile (contiguous 256B rows) into padded smem.
__device__ __forceinline__ void stage_A_async(uint32_t a_dst, const __nv_bfloat16* src) {
    const int tid = threadIdx.x;
    #pragma unroll
    for (int i = tid; i < 128 * 16; i += NTHREADS) {
        int row = i >> 4;
        int cb  = (i & 15) << 4;
        CP_ASYNC16(a_dst + row * ROWB + cb,
                   reinterpret_cast<const char*>(src) + row * 256 + cb);
    }
}

__global__ __launch_bounds__(NTHREADS, 1)
void colbert_fused_kernel(const float* __restrict__ qs,
                          const float* __restrict__ ps,
                          float* __restrict__ out) {
    extern __shared__ char sm[];
    __shared__ float s_red[2][128];
    __shared__ unsigned int s_target;
    __shared__ int s_last;

    const int c = blockIdx.x;
    const int half = blockIdx.y;
    const int cta = c * 2 + half;       // 0..127
    const int tid = threadIdx.x;
    const int lane = tid & 31;
    const int wid = tid >> 5;
    const int wr = wid & 3;
    const int wc = wid >> 2;

    const uint32_t smem_base = smem_u32(sm);
    const uint32_t p_base = smem_base + P_OFF;
    const uint32_t a_base = smem_base + A_OFF;

    // ── Phase A: convert this CTA's 16-row slice of qs to bf16 global. ──
    {
        // rows [cta*16, +16): 16*128 = 2048 fp32 = 256 uint4 outputs; 1 per thread.
        const float4* s4 = reinterpret_cast<const float4*>(qs) + ((size_t)cta * 256 + tid) * 2;
        float4 v0 = s4[0];
        float4 v1 = s4[1];
        __nv_bfloat162 b0 = __floats2bfloat162_rn(v0.x, v0.y);
        __nv_bfloat162 b1 = __floats2bfloat162_rn(v0.z, v0.w);
        __nv_bfloat162 b2 = __floats2bfloat162_rn(v1.x, v1.y);
        __nv_bfloat162 b3 = __floats2bfloat162_rn(v1.z, v1.w);
        uint4 packed;
        packed.x = *reinterpret_cast<uint32_t*>(&b0);
        packed.y = *reinterpret_cast<uint32_t*>(&b1);
        packed.z = *reinterpret_cast<uint32_t*>(&b2);
        packed.w = *reinterpret_cast<uint32_t*>(&b3);
        reinterpret_cast<uint4*>(g_qbf)[(size_t)cta * 256 + tid] = packed;
    }
    __syncthreads();
    if (tid == 0) {
        __threadfence();
        unsigned int old = atomicAdd(&g_qctr, 1u);
        s_target = (old / 128u) * 128u + 128u;   // epoch-safe across graph replays
    }

    // ── Phase B: stage the 512-token p half (fp32 -> bf16, disjoint per CTA). ──
    const float* pg = ps + ((size_t)c * 1024 + (size_t)half * HALF_TOK) * DIM;
    stage_bf16<HALF_TOK>(sm + P_OFF, pg);

    __syncthreads();
    if (tid == 0) {
        while (atomicAdd(&g_qctr, 0u) < s_target) { }   // spin: all q slices converted
        __threadfence();
    }
    __syncthreads();

    // Kick off A tile 0.
    stage_A_async(a_base, g_qbf);
    CP_COMMIT();

    // ldmatrix lane addressing.
    const uint32_t a_lane_off = (uint32_t)((lane & 15) * ROWB + (lane >> 4) * 16);
    const int bgrp = lane >> 3;
    const uint32_t b_lane_off = (uint32_t)(((bgrp >> 1) * 8 + (lane & 7)) * ROWB + (bgrp & 1) * 16);

    // ── Phase C: 16 tiles of 128 q-rows vs 512 tokens. ──
    #pragma unroll 1
    for (int t = 0; t < NTILES; t++) {
        const uint32_t abuf = a_base + (uint32_t)(t & 1) * A_SZ;

        CP_WAIT0();
        __syncthreads();

        uint32_t af[2][8][4];
        #pragma unroll
        for (int mt = 0; mt < 2; mt++) {
            #pragma unroll
            for (int ks = 0; ks < 8; ks++) {
                uint32_t addr = abuf + (uint32_t)((wr * 32 + mt * 16) * ROWB + ks * 32)
                              + a_lane_off;
                LDSM_X4(af[mt][ks], addr);
            }
        }

        if (t + 1 < NTILES) {
            stage_A_async(a_base + (uint32_t)((t + 1) & 1) * A_SZ,
                          g_qbf + (size_t)(t + 1) * 128 * DIM);
        }
        CP_COMMIT();

        float rm[2][2] = {{-3.0e38f, -3.0e38f}, {-3.0e38f, -3.0e38f}};

        #pragma unroll 1
        for (int nb = 0; nb < 8; nb++) {
            const int col0 = nb * 64 + wc * 32;
            float acc[2][4][4];
            #pragma unroll
            for (int mt = 0; mt < 2; mt++)
                #pragma unroll
                for (int nt = 0; nt < 4; nt++)
                    #pragma unroll
                    for (int i = 0; i < 4; i++) acc[mt][nt][i] = 0.0f;

            #pragma unroll
            for (int ks = 0; ks < 8; ks++) {
                uint32_t bf[4][2];
                uint32_t b0 = p_base + (uint32_t)(col0 * ROWB + ks * 32) + b_lane_off;
                uint32_t r[4];
                LDSM_X4(r, b0);
                bf[0][0] = r[0]; bf[0][1] = r[1]; bf[1][0] = r[2]; bf[1][1] = r[3];
                LDSM_X4(r, b0 + 16 * ROWB);
                bf[2][0] = r[0]; bf[2][1] = r[1]; bf[3][0] = r[2]; bf[3][1] = r[3];
                #pragma unroll
                for (int mt = 0; mt < 2; mt++)
                    #pragma unroll
                    for (int nt = 0; nt < 4; nt++)
                        MMA_16816(acc[mt][nt], af[mt][ks], bf[nt]);
            }

            #pragma unroll
            for (int mt = 0; mt < 2; mt++)
                #pragma unroll
                for (int nt = 0; nt < 4; nt++) {
                    rm[mt][0] = fmaxf(rm[mt][0], fmaxf(acc[mt][nt][0], acc[mt][nt][1]));
                    rm[mt][1] = fmaxf(rm[mt][1], fmaxf(acc[mt][nt][2], acc[mt][nt][3]));
                }
        }

        // Reduce across the 4 lanes sharing each row; combine wc groups via smem.
        #pragma unroll
        for (int mt = 0; mt < 2; mt++)
            #pragma unroll
            for (int h = 0; h < 2; h++) {
                float v = rm[mt][h];
                v = fmaxf(v, __shfl_xor_sync(0xffffffffu, v, 1));
                v = fmaxf(v, __shfl_xor_sync(0xffffffffu, v, 2));
                if ((lane & 3) == 0)
                    s_red[wc][wr * 32 + mt * 16 + h * 8 + (lane >> 2)] = v;
            }
        __syncthreads();
        if (tid < 128) {
            float v = fmaxf(s_red[0][tid], s_red[1][tid]);
            g_part[((size_t)c * 2 + half) * QROWS + t * 128 + tid] = v;
        }
    }

    // ── Phase D: last CTA of this c combines halves + sums over n. ──
    __syncthreads();
    if (tid == 0) {
        __threadfence();
        unsigned int old = atomicAdd(&g_cctr[c], 1u);
        s_last = (old & 1u);        // second of the pair this replay
    }
    __syncthreads();
    if (s_last) {
        if (tid == 0) __threadfence();
        __syncthreads();
        const float* p0 = g_part + (size_t)(c * 2 + 0) * QROWS;
        const float* p1 = g_part + (size_t)(c * 2 + 1) * QROWS;
        #pragma unroll
        for (int bb = 0; bb < 8; bb++) {
            int b = wid + bb * 8;
            int qrow = b * 32 + lane;
            float m = fmaxf(p0[qrow], p1[qrow]);
            #pragma unroll
            for (int o = 16; o; o >>= 1) m += __shfl_xor_sync(0xffffffffu, m, o);
            if (lane == 0) out[b * 64 + c] = m;
        }
    }
}

extern "C" void kernel_launch(void* const* d_in, const int* in_sizes, int n_in,
                              void* d_out, int out_size) {
    const float* qs = (const float*)d_in[0];   // (64, 32, 128)
    const float* ps = (const float*)d_in[1];   // (64, 1024, 128)
    float* out = (float*)d_out;                // (64, 64)

    cudaFuncSetAttribute(colbert_fused_kernel,
                         cudaFuncAttributeMaxDynamicSharedMemorySize, SM_TOTAL);
    dim3 grid(64, 2);
    colbert_fused_kernel<<<grid, NTHREADS, SM_TOTAL>>>(qs, ps, out);
}